// round 1
// baseline (speedup 1.0000x reference)
#include <cuda_runtime.h>
#include <cstdint>

// Problem shape (fixed by the dataset):
//   x:       (4, 2048, 4096) fp32  -> M=8192, K=4096 row-major
//   qweight: (512, 11008)   int32  -> K/8 rows, 8 int4 nibbles per int32 along K
//   scales:  (32, 11008)    fp32   -> per-group(128) per-out-channel
//   out:     (4, 2048, 11008) fp32 -> M x N
static constexpr int M_DIM = 8192;
static constexpr int K_DIM = 4096;
static constexpr int N_DIM = 11008;

static constexpr int BM = 128;
static constexpr int BN = 128;
static constexpr int BK = 16;
static constexpr int TM = 8;
static constexpr int TN = 8;
static constexpr int NTHREADS = (BM / TM) * (BN / TN);  // 256

__global__ __launch_bounds__(NTHREADS, 2)
void int4_gemm_f32_kernel(const float* __restrict__ X,
                          const int*   __restrict__ QW,
                          const float* __restrict__ SC,
                          float*       __restrict__ C)
{
    // As transposed (k-major) with +4 padding to break bank conflicts on the
    // transposed stores; Bs holds the dequantized int4 tile.
    __shared__ float As[BK][BM + 4];
    __shared__ float Bs[BK][BN];

    const int tid = threadIdx.x;
    const int tx  = tid & 15;   // n direction (16)
    const int ty  = tid >> 4;   // m direction (16)

    const int m0 = blockIdx.y * BM;
    const int n0 = blockIdx.x * BN;

    // B-tile dequant mapping: one int32 (8 nibbles = 8 k-values) per thread.
    // BK=16 -> 2 qweight rows x 128 columns = 256 int32 = 256 threads.
    const int bn = tid & (BN - 1);  // 0..127
    const int br = tid >> 7;        // 0..1

    float acc[TM][TN];
    #pragma unroll
    for (int i = 0; i < TM; i++)
        #pragma unroll
        for (int j = 0; j < TN; j++) acc[i][j] = 0.0f;

    for (int k0 = 0; k0 < K_DIM; k0 += BK) {
        // ---- Load A tile (BM x BK) as float4, store transposed -----------
        #pragma unroll
        for (int p = 0; p < 2; p++) {
            int f   = tid + p * NTHREADS;   // 0..511
            int row = f >> 2;               // 0..127 (m within tile)
            int kk  = (f & 3) << 2;         // 0,4,8,12
            float4 v = *reinterpret_cast<const float4*>(
                &X[(size_t)(m0 + row) * K_DIM + k0 + kk]);
            As[kk + 0][row] = v.x;
            As[kk + 1][row] = v.y;
            As[kk + 2][row] = v.z;
            As[kk + 3][row] = v.w;
        }

        // ---- Dequantize B tile (BK x BN) into SMEM ------------------------
        // BK=16 never crosses a group boundary (16 | 128), so one scale per
        // (tile, column).
        {
            int krow = (k0 >> 3) + br;  // qweight row index
            unsigned int q = (unsigned int)QW[(size_t)krow * N_DIM + n0 + bn];
            float s = SC[(size_t)(k0 >> 7) * N_DIM + n0 + bn];
            #pragma unroll
            for (int j = 0; j < 8; j++) {
                Bs[br * 8 + j][bn] =
                    ((float)((q >> (4 * j)) & 15u) - 8.0f) * s;
            }
        }
        __syncthreads();

        // ---- Rank-1 updates over the K slice ------------------------------
        #pragma unroll
        for (int k = 0; k < BK; k++) {
            float a[TM], b[TN];
            #pragma unroll
            for (int i = 0; i < TM; i++) a[i] = As[k][ty * TM + i];
            #pragma unroll
            for (int j = 0; j < TN; j++) b[j] = Bs[k][tx * TN + j];
            #pragma unroll
            for (int i = 0; i < TM; i++)
                #pragma unroll
                for (int j = 0; j < TN; j++)
                    acc[i][j] = fmaf(a[i], b[j], acc[i][j]);
        }
        __syncthreads();
    }

    // ---- Writeback: 8x8 per thread, float4 stores -------------------------
    #pragma unroll
    for (int i = 0; i < TM; i++) {
        size_t off = (size_t)(m0 + ty * TM + i) * N_DIM + n0 + tx * TN;
        float4 v0 = make_float4(acc[i][0], acc[i][1], acc[i][2], acc[i][3]);
        float4 v1 = make_float4(acc[i][4], acc[i][5], acc[i][6], acc[i][7]);
        *reinterpret_cast<float4*>(&C[off])     = v0;
        *reinterpret_cast<float4*>(&C[off + 4]) = v1;
    }
}

extern "C" void kernel_launch(void* const* d_in, const int* in_sizes, int n_in,
                              void* d_out, int out_size)
{
    const float* x  = (const float*)d_in[0];
    const int*   qw = (const int*)d_in[1];
    const float* sc = (const float*)d_in[2];
    float*       out = (float*)d_out;

    dim3 grid(N_DIM / BN, M_DIM / BM);  // (86, 64)
    int4_gemm_f32_kernel<<<grid, NTHREADS>>>(x, qw, sc, out);
}

// round 2
// speedup vs baseline: 1.0007x; 1.0007x over previous
#include <cuda_runtime.h>
#include <cstdint>

// Problem shape (fixed by the dataset):
//   x:       (4, 2048, 4096) fp32  -> M=8192, K=4096 row-major
//   qweight: (512, 11008)   int32  -> K/8 rows, 8 int4 nibbles per int32 along K
//   scales:  (32, 11008)    fp32   -> per-group(128) per-out-channel
//   out:     (4, 2048, 11008) fp32 -> M x N
static constexpr int M_DIM = 8192;
static constexpr int K_DIM = 4096;
static constexpr int N_DIM = 11008;

static constexpr int BM = 128;
static constexpr int BN = 128;
static constexpr int BK = 16;
static constexpr int TM = 8;
static constexpr int TN = 8;
static constexpr int NTHREADS = (BM / TM) * (BN / TN);  // 256

__global__ __launch_bounds__(NTHREADS, 2)
void int4_gemm_f32_kernel(const float* __restrict__ X,
                          const int*   __restrict__ QW,
                          const float* __restrict__ SC,
                          float*       __restrict__ C)
{
    // As transposed (k-major) with +4 padding to break bank conflicts on the
    // transposed stores; Bs holds the dequantized int4 tile.
    __shared__ float As[BK][BM + 4];
    __shared__ float Bs[BK][BN];

    const int tid = threadIdx.x;
    const int tx  = tid & 15;   // n direction (16)
    const int ty  = tid >> 4;   // m direction (16)

    const int m0 = blockIdx.y * BM;
    const int n0 = blockIdx.x * BN;

    // B-tile dequant mapping: one int32 (8 nibbles = 8 k-values) per thread.
    // BK=16 -> 2 qweight rows x 128 columns = 256 int32 = 256 threads.
    const int bn = tid & (BN - 1);  // 0..127
    const int br = tid >> 7;        // 0..1

    float acc[TM][TN];
    #pragma unroll
    for (int i = 0; i < TM; i++)
        #pragma unroll
        for (int j = 0; j < TN; j++) acc[i][j] = 0.0f;

    for (int k0 = 0; k0 < K_DIM; k0 += BK) {
        // ---- Load A tile (BM x BK) as float4, store transposed -----------
        #pragma unroll
        for (int p = 0; p < 2; p++) {
            int f   = tid + p * NTHREADS;   // 0..511
            int row = f >> 2;               // 0..127 (m within tile)
            int kk  = (f & 3) << 2;         // 0,4,8,12
            float4 v = *reinterpret_cast<const float4*>(
                &X[(size_t)(m0 + row) * K_DIM + k0 + kk]);
            As[kk + 0][row] = v.x;
            As[kk + 1][row] = v.y;
            As[kk + 2][row] = v.z;
            As[kk + 3][row] = v.w;
        }

        // ---- Dequantize B tile (BK x BN) into SMEM ------------------------
        // BK=16 never crosses a group boundary (16 | 128), so one scale per
        // (tile, column).
        {
            int krow = (k0 >> 3) + br;  // qweight row index
            unsigned int q = (unsigned int)QW[(size_t)krow * N_DIM + n0 + bn];
            float s = SC[(size_t)(k0 >> 7) * N_DIM + n0 + bn];
            #pragma unroll
            for (int j = 0; j < 8; j++) {
                Bs[br * 8 + j][bn] =
                    ((float)((q >> (4 * j)) & 15u) - 8.0f) * s;
            }
        }
        __syncthreads();

        // ---- Rank-1 updates over the K slice ------------------------------
        #pragma unroll
        for (int k = 0; k < BK; k++) {
            float a[TM], b[TN];
            #pragma unroll
            for (int i = 0; i < TM; i++) a[i] = As[k][ty * TM + i];
            #pragma unroll
            for (int j = 0; j < TN; j++) b[j] = Bs[k][tx * TN + j];
            #pragma unroll
            for (int i = 0; i < TM; i++)
                #pragma unroll
                for (int j = 0; j < TN; j++)
                    acc[i][j] = fmaf(a[i], b[j], acc[i][j]);
        }
        __syncthreads();
    }

    // ---- Writeback: 8x8 per thread, float4 stores -------------------------
    #pragma unroll
    for (int i = 0; i < TM; i++) {
        size_t off = (size_t)(m0 + ty * TM + i) * N_DIM + n0 + tx * TN;
        float4 v0 = make_float4(acc[i][0], acc[i][1], acc[i][2], acc[i][3]);
        float4 v1 = make_float4(acc[i][4], acc[i][5], acc[i][6], acc[i][7]);
        *reinterpret_cast<float4*>(&C[off])     = v0;
        *reinterpret_cast<float4*>(&C[off + 4]) = v1;
    }
}

extern "C" void kernel_launch(void* const* d_in, const int* in_sizes, int n_in,
                              void* d_out, int out_size)
{
    const float* x  = (const float*)d_in[0];
    const int*   qw = (const int*)d_in[1];
    const float* sc = (const float*)d_in[2];
    float*       out = (float*)d_out;

    dim3 grid(N_DIM / BN, M_DIM / BM);  // (86, 64)
    int4_gemm_f32_kernel<<<grid, NTHREADS>>>(x, qw, sc, out);
}

// round 3
// speedup vs baseline: 1.0010x; 1.0003x over previous
#include <cuda_runtime.h>
#include <cstdint>

// Problem shape (fixed by the dataset):
//   x:       (4, 2048, 4096) fp32  -> M=8192, K=4096 row-major
//   qweight: (512, 11008)   int32  -> K/8 rows, 8 int4 nibbles per int32 along K
//   scales:  (32, 11008)    fp32   -> per-group(128) per-out-channel
//   out:     (4, 2048, 11008) fp32 -> M x N
static constexpr int M_DIM = 8192;
static constexpr int K_DIM = 4096;
static constexpr int N_DIM = 11008;

static constexpr int BM = 128;
static constexpr int BN = 128;
static constexpr int BK = 16;
static constexpr int TM = 8;
static constexpr int TN = 8;
static constexpr int NTHREADS = (BM / TM) * (BN / TN);  // 256

__global__ __launch_bounds__(NTHREADS, 2)
void int4_gemm_f32_kernel(const float* __restrict__ X,
                          const int*   __restrict__ QW,
                          const float* __restrict__ SC,
                          float*       __restrict__ C)
{
    // As transposed (k-major) with +4 padding to break bank conflicts on the
    // transposed stores; Bs holds the dequantized int4 tile.
    __shared__ float As[BK][BM + 4];
    __shared__ float Bs[BK][BN];

    const int tid = threadIdx.x;
    const int tx  = tid & 15;   // n direction (16)
    const int ty  = tid >> 4;   // m direction (16)

    const int m0 = blockIdx.y * BM;
    const int n0 = blockIdx.x * BN;

    // B-tile dequant mapping: one int32 (8 nibbles = 8 k-values) per thread.
    // BK=16 -> 2 qweight rows x 128 columns = 256 int32 = 256 threads.
    const int bn = tid & (BN - 1);  // 0..127
    const int br = tid >> 7;        // 0..1

    float acc[TM][TN];
    #pragma unroll
    for (int i = 0; i < TM; i++)
        #pragma unroll
        for (int j = 0; j < TN; j++) acc[i][j] = 0.0f;

    for (int k0 = 0; k0 < K_DIM; k0 += BK) {
        // ---- Load A tile (BM x BK) as float4, store transposed -----------
        #pragma unroll
        for (int p = 0; p < 2; p++) {
            int f   = tid + p * NTHREADS;   // 0..511
            int row = f >> 2;               // 0..127 (m within tile)
            int kk  = (f & 3) << 2;         // 0,4,8,12
            float4 v = *reinterpret_cast<const float4*>(
                &X[(size_t)(m0 + row) * K_DIM + k0 + kk]);
            As[kk + 0][row] = v.x;
            As[kk + 1][row] = v.y;
            As[kk + 2][row] = v.z;
            As[kk + 3][row] = v.w;
        }

        // ---- Dequantize B tile (BK x BN) into SMEM ------------------------
        // BK=16 never crosses a group boundary (16 | 128), so one scale per
        // (tile, column).
        {
            int krow = (k0 >> 3) + br;  // qweight row index
            unsigned int q = (unsigned int)QW[(size_t)krow * N_DIM + n0 + bn];
            float s = SC[(size_t)(k0 >> 7) * N_DIM + n0 + bn];
            #pragma unroll
            for (int j = 0; j < 8; j++) {
                Bs[br * 8 + j][bn] =
                    ((float)((q >> (4 * j)) & 15u) - 8.0f) * s;
            }
        }
        __syncthreads();

        // ---- Rank-1 updates over the K slice ------------------------------
        #pragma unroll
        for (int k = 0; k < BK; k++) {
            float a[TM], b[TN];
            #pragma unroll
            for (int i = 0; i < TM; i++) a[i] = As[k][ty * TM + i];
            #pragma unroll
            for (int j = 0; j < TN; j++) b[j] = Bs[k][tx * TN + j];
            #pragma unroll
            for (int i = 0; i < TM; i++)
                #pragma unroll
                for (int j = 0; j < TN; j++)
                    acc[i][j] = fmaf(a[i], b[j], acc[i][j]);
        }
        __syncthreads();
    }

    // ---- Writeback: 8x8 per thread, float4 stores -------------------------
    #pragma unroll
    for (int i = 0; i < TM; i++) {
        size_t off = (size_t)(m0 + ty * TM + i) * N_DIM + n0 + tx * TN;
        float4 v0 = make_float4(acc[i][0], acc[i][1], acc[i][2], acc[i][3]);
        float4 v1 = make_float4(acc[i][4], acc[i][5], acc[i][6], acc[i][7]);
        *reinterpret_cast<float4*>(&C[off])     = v0;
        *reinterpret_cast<float4*>(&C[off + 4]) = v1;
    }
}

extern "C" void kernel_launch(void* const* d_in, const int* in_sizes, int n_in,
                              void* d_out, int out_size)
{
    const float* x  = (const float*)d_in[0];
    const int*   qw = (const int*)d_in[1];
    const float* sc = (const float*)d_in[2];
    float*       out = (float*)d_out;

    dim3 grid(N_DIM / BN, M_DIM / BM);  // (86, 64)
    int4_gemm_f32_kernel<<<grid, NTHREADS>>>(x, qw, sc, out);
}